// round 7
// baseline (speedup 1.0000x reference)
#include <cuda_runtime.h>

// EnergyGatedDeltaModel — GB300 sm_103a
// R6: bit-exact emulation of XLA:CPU (aarch64/NEON, fast-math) semantics:
//  - reductions (dot/einsum/sum): LLVM loop-vectorized, VF=4 x IC=4 ->
//    16 fma-chained accumulators A[c] over elements {16m+c}, parts folded
//    sequentially ((A0+A1)+A2)+A3 vectorwise, horizontal (V0+V2)+(V1+V3).
//  - fusions contract mul+add -> fma (Mn = fma(u,k,M)); u = sub(k, div(v,dn)).
//  - Eigen GEMMs (encoder FFN, readout): per-output sequential fma chain over
//    k ascending, bias as separate add.
//  - gate: fast path analytic dE (certified sign when |dE|>=1.0 vs reference's
//    <=~0.3 norm rounding); marginal steps run exact dual 1024-chain NEON sums.

#define B_ 512
#define L_ 2048
#define H_ 32
#define V_ 64
#define STEPS (L_ - 1)
#define THRESH 1.0f

__device__ float g_table[V_ * H_];
__device__ float g_ksq[V_];     // NEON-ordered (k*k).sum
__device__ float g_denom[V_];   // ksq + 1e-6
__device__ int   g_writes;

// NEON VF4xIC4 reduction of 32 products x[i]*y[i] (fma-chained accumulators).
__device__ __forceinline__ float neon_dot32(const float* x, const float* y) {
    float A[16];
#pragma unroll
    for (int c = 0; c < 16; c++) A[c] = __fmul_rn(x[c], y[c]);        // m=0: fma into 0
#pragma unroll
    for (int c = 0; c < 16; c++) A[c] = fmaf(x[16 + c], y[16 + c], A[c]);  // m=1
    float V[4];
#pragma unroll
    for (int l = 0; l < 4; l++)
        V[l] = __fadd_rn(__fadd_rn(__fadd_rn(A[l], A[4 + l]), A[8 + l]), A[12 + l]);
    return __fadd_rn(__fadd_rn(V[0], V[2]), __fadd_rn(V[1], V[3]));
}

// Same tree for a plain 32-sum of terms t[i].
__device__ __forceinline__ float neon_sum32(const float* t) {
    float A[16];
#pragma unroll
    for (int c = 0; c < 16; c++) A[c] = __fadd_rn(t[c], t[16 + c]);
    float V[4];
#pragma unroll
    for (int l = 0; l < 4; l++)
        V[l] = __fadd_rn(__fadd_rn(__fadd_rn(A[l], A[4 + l]), A[8 + l]), A[12 + l]);
    return __fadd_rn(__fadd_rn(V[0], V[2]), __fadd_rn(V[1], V[3]));
}

// ---------------------------------------------------------------------------
// Precompute: per-vocab encoder. Eigen GEMM chains; NEON-ordered LN reductions.
// ---------------------------------------------------------------------------
__global__ void precompute_kernel(const float* __restrict__ embed,
                                  const float* __restrict__ w1,
                                  const float* __restrict__ b1,
                                  const float* __restrict__ w2,
                                  const float* __restrict__ b2,
                                  const float* __restrict__ ln_g,
                                  const float* __restrict__ ln_b)
{
    int v = threadIdx.x;
    if (v == 0) g_writes = 0;
    if (v >= V_) return;

    float h[H_];
#pragma unroll
    for (int i = 0; i < H_; i++) h[i] = embed[v * H_ + i];

    float acc[H_];
#pragma unroll
    for (int i = 0; i < H_; i++) acc[i] = 0.0f;

    for (int j = 0; j < 2 * H_; j++) {
        float s = 0.0f;                        // h @ w1: Eigen seq fma, k ascending
#pragma unroll
        for (int i = 0; i < H_; i++) s = fmaf(h[i], w1[i * 2 * H_ + j], s);
        s = __fadd_rn(s, b1[j]);               // + b1 separate
        s = fmaxf(s, 0.0f);                    // relu
#pragma unroll
        for (int i = 0; i < H_; i++) acc[i] = fmaf(s, w2[j * H_ + i], acc[i]);
    }

    float x[H_];
#pragma unroll
    for (int i = 0; i < H_; i++) {
        float ff = __fadd_rn(acc[i], b2[i]);
        x[i] = __fadd_rn(h[i], ff);
    }
    float mu = __fmul_rn(neon_sum32(x), 1.0f / H_);
    float d[H_], sq[H_];
#pragma unroll
    for (int i = 0; i < H_; i++) {
        d[i] = __fsub_rn(x[i], mu);
        sq[i] = __fmul_rn(d[i], d[i]);
    }
    float var = __fmul_rn(neon_sum32(sq), 1.0f / H_);
    float rs = __fdiv_rn(1.0f, __fsqrt_rn(__fadd_rn(var, 1e-5f)));

    float y[H_];
#pragma unroll
    for (int i = 0; i < H_; i++) {
        y[i] = __fadd_rn(__fmul_rn(__fmul_rn(d[i], rs), ln_g[i]), ln_b[i]);
        g_table[v * H_ + i] = y[i];
        sq[i] = __fmul_rn(y[i], y[i]);
    }
    float ksq = neon_sum32(sq);                // NEON-ordered (k*k).sum
    g_ksq[v]   = ksq;
    g_denom[v] = __fadd_rn(ksq, 1e-6f);
}

// ---------------------------------------------------------------------------
// Scan: one warp per batch, lane i holds row i of M.
// ---------------------------------------------------------------------------
__global__ void __launch_bounds__(32) scan_kernel(const int* __restrict__ seq,
                                                  const float* __restrict__ w_read,
                                                  const float* __restrict__ b_read,
                                                  const float* __restrict__ w_out,
                                                  const float* __restrict__ b_out,
                                                  float* __restrict__ out)
{
    __shared__ __align__(16) float tsh[V_ * H_];
    __shared__ __align__(16) float Msh[H_ * H_];
    __shared__ __align__(16) float Mnsh[H_ * H_];
    __shared__ float dnsh[V_];
    __shared__ float kssh[V_];
    __shared__ int   toks[32];
    __shared__ float scratch[H_];

    const int lane = threadIdx.x;
    const int b    = blockIdx.x;
    const unsigned FULL = 0xffffffffu;

    for (int i = lane; i < V_ * H_; i += 32) tsh[i] = g_table[i];
    dnsh[lane]      = g_denom[lane];
    dnsh[lane + 32] = g_denom[lane + 32];
    kssh[lane]      = g_ksq[lane];
    kssh[lane + 32] = g_ksq[lane + 32];
    __syncwarp();

    float M[H_];
#pragma unroll
    for (int j = 0; j < H_; j++) M[j] = 0.0f;

    int writes = 0;
    const int* sb = seq + b * L_;

    for (int t0 = 0; t0 < STEPS; t0 += 32) {
        toks[lane] = sb[t0 + lane];   // lane31 of last chunk loads t=2047; unused below
        __syncwarp();
        const int tend = (STEPS - t0) < 32 ? (STEPS - t0) : 32;

        for (int tt = 0; tt < tend; tt++) {
            const int tok = toks[tt];
            float kv[H_];
            {
                const float4* kp = (const float4*)(tsh + tok * H_);
#pragma unroll
                for (int q = 0; q < 8; q++) {
                    float4 f = kp[q];
                    kv[4 * q + 0] = f.x; kv[4 * q + 1] = f.y;
                    kv[4 * q + 2] = f.z; kv[4 * q + 3] = f.w;
                }
            }
            const float ki = tsh[tok * H_ + lane];
            const float dn = dnsh[tok];
            const float ks = kssh[tok];

            // v_i: NEON VF4xIC4 strength-reduced dot (fma chains)
            const float v = neon_dot32(M, kv);

            // u_i = k_i - v_i/denom  (div then sub, unfused)
            const float u = __fsub_rn(ki, __fdiv_rn(v, dn));

            // Mn = fma(u, k, M)  (fast-math contraction in the fusion)
            float Mn[H_];
#pragma unroll
            for (int j = 0; j < H_; j++) Mn[j] = fmaf(u, kv[j], M[j]);

            // fast gate: dE = 2 u.v + ||u||^2 ksq  (butterflies, cert. |dE|>=1)
            float suv = __fmul_rn(u, v);
            float suu = __fmul_rn(u, u);
#pragma unroll
            for (int o = 16; o > 0; o >>= 1) {
                suv += __shfl_xor_sync(FULL, suv, o);
                suu += __shfl_xor_sync(FULL, suu, o);
            }
            const float dE = __fadd_rn(__fadd_rn(suv, suv), __fmul_rn(suu, ks));

            int gate;
            if (fabsf(dE) >= THRESH) {
                gate = dE > 0.0f;
            } else {
                // exact: both 1024-sums in NEON order (16 chains over {16m+c})
                {
                    float4* mr  = (float4*)(Msh  + lane * H_);
                    float4* mnr = (float4*)(Mnsh + lane * H_);
#pragma unroll
                    for (int q = 0; q < 8; q++) {
                        mr[q]  = make_float4(M[4*q], M[4*q+1], M[4*q+2], M[4*q+3]);
                        mnr[q] = make_float4(Mn[4*q], Mn[4*q+1], Mn[4*q+2], Mn[4*q+3]);
                    }
                }
                __syncwarp();
                const float* P = (lane < 16) ? Msh : Mnsh;
                const int c = lane & 15;
                float a = 0.0f;
#pragma unroll
                for (int m = 0; m < 64; m++) {
                    float s = P[16 * m + c];
                    a = fmaf(s, s, a);
                }
                __syncwarp();
                float Vo[4], Vn[4];
#pragma unroll
                for (int l = 0; l < 4; l++) {
                    float a0 = __shfl_sync(FULL, a, l);
                    float a1 = __shfl_sync(FULL, a, l + 4);
                    float a2 = __shfl_sync(FULL, a, l + 8);
                    float a3 = __shfl_sync(FULL, a, l + 12);
                    Vo[l] = __fadd_rn(__fadd_rn(__fadd_rn(a0, a1), a2), a3);
                    float c0 = __shfl_sync(FULL, a, 16 + l);
                    float c1 = __shfl_sync(FULL, a, 20 + l);
                    float c2 = __shfl_sync(FULL, a, 24 + l);
                    float c3 = __shfl_sync(FULL, a, 28 + l);
                    Vn[l] = __fadd_rn(__fadd_rn(__fadd_rn(c0, c1), c2), c3);
                }
                const float eo = __fadd_rn(__fadd_rn(Vo[0], Vo[2]), __fadd_rn(Vo[1], Vo[3]));
                const float en = __fadd_rn(__fadd_rn(Vn[0], Vn[2]), __fadd_rn(Vn[1], Vn[3]));
                gate = en > eo;
            }

            if (gate) {
                writes++;
#pragma unroll
                for (int j = 0; j < H_; j++) M[j] = Mn[j];
            }
        }
        __syncwarp();
    }

    // -------- readout --------
    const int qtok = sb[L_ - 1];
    float ctx;
    {
        float qv[H_];
        const float4* kp = (const float4*)(tsh + qtok * H_);
#pragma unroll
        for (int q = 0; q < 8; q++) {
            float4 f = kp[q];
            qv[4 * q + 0] = f.x; qv[4 * q + 1] = f.y;
            qv[4 * q + 2] = f.z; qv[4 * q + 3] = f.w;
        }
        ctx = neon_dot32(M, qv);               // einsum matvec, NEON order
    }

    scratch[lane] = ctx;
    __syncwarp();
    float r = 0.0f;                            // ctx @ w_read: Eigen seq fma
#pragma unroll
    for (int j = 0; j < H_; j++) r = fmaf(scratch[j], w_read[j * H_ + lane], r);
    r = __fadd_rn(r, b_read[lane]);
    __syncwarp();
    scratch[lane] = r;
    __syncwarp();

    float o0 = 0.0f, o1 = 0.0f;                // @ w_out
#pragma unroll
    for (int j = 0; j < H_; j++) {
        const float rj = scratch[j];
        o0 = fmaf(rj, w_out[j * V_ + lane], o0);
        o1 = fmaf(rj, w_out[j * V_ + lane + H_], o1);
    }
    out[b * V_ + lane]      = __fadd_rn(o0, b_out[lane]);
    out[b * V_ + lane + H_] = __fadd_rn(o1, b_out[lane + H_]);

    if (lane == 0) atomicAdd(&g_writes, writes);
}

// ---------------------------------------------------------------------------
__global__ void finalize_kernel(float* __restrict__ out, int out_size)
{
    if (out_size > B_ * V_)
        out[B_ * V_] = __fdiv_rn((float)g_writes, (float)(STEPS * B_));
}

extern "C" void kernel_launch(void* const* d_in, const int* in_sizes, int n_in,
                              void* d_out, int out_size)
{
    const int*   seq    = (const int*)d_in[0];
    const float* embed  = (const float*)d_in[1];
    const float* w1     = (const float*)d_in[2];
    const float* b1     = (const float*)d_in[3];
    const float* w2     = (const float*)d_in[4];
    const float* b2     = (const float*)d_in[5];
    const float* ln_g   = (const float*)d_in[6];
    const float* ln_b   = (const float*)d_in[7];
    const float* w_read = (const float*)d_in[8];
    const float* b_read = (const float*)d_in[9];
    const float* w_out  = (const float*)d_in[10];
    const float* b_out  = (const float*)d_in[11];
    float* out = (float*)d_out;

    precompute_kernel<<<1, 64>>>(embed, w1, b1, w2, b2, ln_g, ln_b);
    scan_kernel<<<B_, 32>>>(seq, w_read, b_read, w_out, b_out, out);
    finalize_kernel<<<1, 1>>>(out, out_size);
}